// round 15
// baseline (speedup 1.0000x reference)
#include <cuda_runtime.h>
#include <cuda_bf16.h>
#include <math.h>
#include <stdint.h>

// ---------------- problem constants ----------------
#define NBATCH   2
#define SEQLEN   512
#define D_INNER  4096
#define D_STATE  16
#define DT_RANK  128
#define NROWS    (NBATCH * SEQLEN)          // 1024
#define XPC      (DT_RANK + 2 * D_STATE)    // 160
#define KSPLIT   16

// ---------------- scratch ----------------
__device__ float g_part[KSPLIT * NROWS * XPC];
__device__ float g_xp[NROWS * XPC];
__device__ float g_dt[NROWS * D_INNER];

__device__ __nv_bfloat16 g_xhi[NROWS * D_INNER], g_xlo[NROWS * D_INNER];
__device__ __nv_bfloat16 g_whi[XPC * D_INNER],   g_wlo[XPC * D_INNER];
__device__ __nv_bfloat16 g_xphi[NROWS * DT_RANK], g_xplo[NROWS * DT_RANK];
__device__ __nv_bfloat16 g_dwhi[D_INNER * DT_RANK], g_dwlo[D_INNER * DT_RANK];

// ---------------- helpers ----------------
__device__ __forceinline__ float ex2f(float v) {
    float r; asm("ex2.approx.ftz.f32 %0, %1;" : "=f"(r) : "f"(v)); return r;
}
__device__ __forceinline__ float softplusf(float z) {
    return fmaxf(z, 0.0f) + log1pf(__expf(-fabsf(z)));
}
__device__ __forceinline__ void cp16(void* dst, const void* src) {
    unsigned s = (unsigned)__cvta_generic_to_shared(dst);
    asm volatile("cp.async.cg.shared.global [%0], [%1], 16;" :: "r"(s), "l"(src));
}
__device__ __forceinline__ void cp_commit() { asm volatile("cp.async.commit_group;"); }
template <int N>
__device__ __forceinline__ void cp_wait() { asm volatile("cp.async.wait_group %0;" :: "n"(N)); }

__device__ __forceinline__ void split2(float x, float y, uint32_t& hi, uint32_t& lo) {
    __nv_bfloat16 hx = __float2bfloat16(x);
    __nv_bfloat16 hy = __float2bfloat16(y);
    float rx = x - __bfloat162float(hx);
    float ry = y - __bfloat162float(hy);
    __nv_bfloat162 H; H.x = hx; H.y = hy;
    __nv_bfloat162 L = __floats2bfloat162_rn(rx, ry);
    hi = *reinterpret_cast<uint32_t*>(&H);
    lo = *reinterpret_cast<uint32_t*>(&L);
}
__device__ __forceinline__ void split4(float4 v, uint2& hi, uint2& lo) {
    split2(v.x, v.y, hi.x, lo.x);
    split2(v.z, v.w, hi.y, lo.y);
}

__device__ __forceinline__ void mma16816(float c[4],
    uint32_t a0, uint32_t a1, uint32_t a2, uint32_t a3, uint32_t b0, uint32_t b1)
{
    asm volatile(
        "mma.sync.aligned.m16n8k16.row.col.f32.bf16.bf16.f32 "
        "{%0,%1,%2,%3}, {%4,%5,%6,%7}, {%8,%9}, {%0,%1,%2,%3};"
        : "+f"(c[0]), "+f"(c[1]), "+f"(c[2]), "+f"(c[3])
        : "r"(a0), "r"(a1), "r"(a2), "r"(a3), "r"(b0), "r"(b1));
}
__device__ __forceinline__ uint32_t ldu(const __nv_bfloat16* p) {
    return *reinterpret_cast<const uint32_t*>(p);
}

#define LDK 24   // bf16 smem row stride: 48B, 16B-aligned, conflict-free

// =====================================================================
// convert_xw: split x (4.2M) and x_proj_w (0.65M) into bf16 hi/lo
// =====================================================================
#define XN4 (NROWS * D_INNER / 4)
#define WN4 (XPC * D_INNER / 4)

__global__ __launch_bounds__(256)
void convert_xw(const float* __restrict__ x, const float* __restrict__ w)
{
    int i = blockIdx.x * 256 + threadIdx.x;
    if (i < XN4) {
        float4 v = ((const float4*)x)[i];
        uint2 hi, lo; split4(v, hi, lo);
        *(uint2*)&g_xhi[4 * (size_t)i] = hi;
        *(uint2*)&g_xlo[4 * (size_t)i] = lo;
    } else if (i < XN4 + WN4) {
        int j = i - XN4;
        float4 v = ((const float4*)w)[j];
        uint2 hi, lo; split4(v, hi, lo);
        *(uint2*)&g_whi[4 * (size_t)j] = hi;
        *(uint2*)&g_wlo[4 * (size_t)j] = lo;
    }
}

// =====================================================================
// GEMM1 (bf16 tensor, 3-stage cp.async):
// part[z][row][c] = sum_{k in slice z} x[row][k]*w[c][k]
// grid (16 Mtiles of 64, 16 ksplits), 256 thr (8 warps: 2M x 4N).
// Kslice 256 = 16 chunks of k16.
// =====================================================================
#define G1_NC 16

__global__ __launch_bounds__(256)
void gemm1_kernel()
{
    __shared__ __nv_bfloat16 AH[3][64][LDK],  AL[3][64][LDK];
    __shared__ __nv_bfloat16 BH[3][160][LDK], BL[3][160][LDK];

    const int tid = threadIdx.x;
    const int m0 = blockIdx.x * 64;
    const int k0 = blockIdx.y * 256;

    const int lane = tid & 31, wid = tid >> 5;
    const int wm = (wid >> 2) * 32;
    const int wn = (wid & 3) * 40;
    const int g = lane >> 2, t2 = (lane & 3) * 2;

    auto load = [&](int c, int st) {
        const int kk = k0 + c * 16;
        for (int s = tid; s < 896; s += 256) {
            if (s < 256) {
                int arr = s >> 7, r = (s >> 1) & 63, half = s & 1;
                const __nv_bfloat16* src =
                    (arr ? g_xlo : g_xhi) + (size_t)(m0 + r) * D_INNER + kk + half * 8;
                __nv_bfloat16* dst = arr ? &AL[st][r][half * 8] : &AH[st][r][half * 8];
                cp16(dst, src);
            } else {
                int s2 = s - 256;
                int arr = s2 / 320, idx = s2 % 320;
                int r = idx >> 1, half = idx & 1;
                const __nv_bfloat16* src =
                    (arr ? g_wlo : g_whi) + (size_t)r * D_INNER + kk + half * 8;
                __nv_bfloat16* dst = arr ? &BL[st][r][half * 8] : &BH[st][r][half * 8];
                cp16(dst, src);
            }
        }
    };

    float acc[2][5][4];
#pragma unroll
    for (int i = 0; i < 2; i++)
#pragma unroll
        for (int j = 0; j < 5; j++)
#pragma unroll
            for (int v = 0; v < 4; v++) acc[i][j][v] = 0.0f;

    load(0, 0); cp_commit();
    load(1, 1); cp_commit();

    for (int c = 0; c < G1_NC; c++) {
        if (c + 1 < G1_NC) cp_wait<1>(); else cp_wait<0>();
        __syncthreads();
        if (c + 2 < G1_NC) { load(c + 2, (c + 2) % 3); cp_commit(); }

        const int st = c % 3;
        uint32_t ah[2][4], al[2][4];
#pragma unroll
        for (int mt = 0; mt < 2; mt++) {
            const int r = wm + mt * 16 + g;
            ah[mt][0] = ldu(&AH[st][r][t2]);      ah[mt][1] = ldu(&AH[st][r + 8][t2]);
            ah[mt][2] = ldu(&AH[st][r][t2 + 8]);  ah[mt][3] = ldu(&AH[st][r + 8][t2 + 8]);
            al[mt][0] = ldu(&AL[st][r][t2]);      al[mt][1] = ldu(&AL[st][r + 8][t2]);
            al[mt][2] = ldu(&AL[st][r][t2 + 8]);  al[mt][3] = ldu(&AL[st][r + 8][t2 + 8]);
        }
#pragma unroll
        for (int nt = 0; nt < 5; nt++) {
            const int n = wn + nt * 8 + g;
            uint32_t bh0 = ldu(&BH[st][n][t2]), bh1 = ldu(&BH[st][n][t2 + 8]);
            uint32_t bl0 = ldu(&BL[st][n][t2]), bl1 = ldu(&BL[st][n][t2 + 8]);
#pragma unroll
            for (int mt = 0; mt < 2; mt++) {
                mma16816(acc[mt][nt], ah[mt][0], ah[mt][1], ah[mt][2], ah[mt][3], bh0, bh1);
                mma16816(acc[mt][nt], ah[mt][0], ah[mt][1], ah[mt][2], ah[mt][3], bl0, bl1);
                mma16816(acc[mt][nt], al[mt][0], al[mt][1], al[mt][2], al[mt][3], bh0, bh1);
            }
        }
    }

    float* outz = g_part + (size_t)blockIdx.y * NROWS * XPC;
#pragma unroll
    for (int mt = 0; mt < 2; mt++) {
        const int r = m0 + wm + mt * 16 + g;
#pragma unroll
        for (int nt = 0; nt < 5; nt++) {
            const int col = wn + nt * 8 + t2;
            *(float2*)&outz[(size_t)r * XPC + col]       = make_float2(acc[mt][nt][0], acc[mt][nt][1]);
            *(float2*)&outz[(size_t)(r + 8) * XPC + col] = make_float2(acc[mt][nt][2], acc[mt][nt][3]);
        }
    }
}

// =====================================================================
// reduce_conv: g_xp = sum_z g_part[z]; also split xp[:, :128] and dtw
// to bf16 hi/lo for GEMM2.
// =====================================================================
#define RN4  (NROWS * XPC / 4)          // 40960
#define DW4  (D_INNER * DT_RANK / 4)    // 131072

__global__ __launch_bounds__(256)
void reduce_conv(const float* __restrict__ dtw)
{
    int i = blockIdx.x * 256 + threadIdx.x;
    if (i < RN4) {
        const float4* p = (const float4*)g_part;
        float4 s = p[i];
#pragma unroll
        for (int z = 1; z < KSPLIT; z++) {
            float4 v = p[(size_t)z * RN4 + i];
            s.x += v.x; s.y += v.y; s.z += v.z; s.w += v.w;
        }
        ((float4*)g_xp)[i] = s;
        int row = i / (XPC / 4), col4 = i % (XPC / 4);
        if (col4 < DT_RANK / 4) {
            uint2 hi, lo; split4(s, hi, lo);
            size_t o = (size_t)row * DT_RANK + col4 * 4;
            *(uint2*)&g_xphi[o] = hi;
            *(uint2*)&g_xplo[o] = lo;
        }
    } else if (i < RN4 + DW4) {
        int j = i - RN4;
        float4 v = ((const float4*)dtw)[j];
        uint2 hi, lo; split4(v, hi, lo);
        *(uint2*)&g_dwhi[4 * (size_t)j] = hi;
        *(uint2*)&g_dwlo[4 * (size_t)j] = lo;
    }
}

// =====================================================================
// GEMM2 (bf16 tensor, 3-stage cp.async):
// g_dt[row][d] = softplus(sum_r xp[row][r]*dtw[d][r] + b[d])
// grid (8 Mtiles of 128, 32 Ntiles of 128), 256 thr (8 warps: 4M x 2N).
// K=128 = 8 chunks of 16.
// =====================================================================
#define G2_NC 8

__global__ __launch_bounds__(256)
void gemm2_kernel(const float* __restrict__ dtb)
{
    __shared__ __nv_bfloat16 AH[3][128][LDK], AL[3][128][LDK];
    __shared__ __nv_bfloat16 BH[3][128][LDK], BL[3][128][LDK];

    const int tid = threadIdx.x;
    const int m0 = blockIdx.x * 128;
    const int n0 = blockIdx.y * 128;

    const int lane = tid & 31, wid = tid >> 5;
    const int wm = (wid >> 1) * 32;
    const int wn = (wid & 1) * 64;
    const int g = lane >> 2, t2 = (lane & 3) * 2;

    auto load = [&](int c, int st) {
        const int kk = c * 16;
        for (int s = tid; s < 1024; s += 256) {
            int which = s >> 9;          // 0 = A, 1 = B
            int s2 = s & 511;
            int arr = s2 >> 8, idx = s2 & 255;
            int r = idx >> 1, half = idx & 1;
            const __nv_bfloat16* src;
            __nv_bfloat16* dst;
            if (which == 0) {
                src = (arr ? g_xplo : g_xphi) + (size_t)(m0 + r) * DT_RANK + kk + half * 8;
                dst = arr ? &AL[st][r][half * 8] : &AH[st][r][half * 8];
            } else {
                src = (arr ? g_dwlo : g_dwhi) + (size_t)(n0 + r) * DT_RANK + kk + half * 8;
                dst = arr ? &BL[st][r][half * 8] : &BH[st][r][half * 8];
            }
            cp16(dst, src);
        }
    };

    float acc[2][8][4];
#pragma unroll
    for (int i = 0; i < 2; i++)
#pragma unroll
        for (int j = 0; j < 8; j++)
#pragma unroll
            for (int v = 0; v < 4; v++) acc[i][j][v] = 0.0f;

    load(0, 0); cp_commit();
    load(1, 1); cp_commit();

    for (int c = 0; c < G2_NC; c++) {
        if (c + 1 < G2_NC) cp_wait<1>(); else cp_wait<0>();
        __syncthreads();
        if (c + 2 < G2_NC) { load(c + 2, (c + 2) % 3); cp_commit(); }

        const int st = c % 3;
        uint32_t ah[2][4], al[2][4];
#pragma unroll
        for (int mt = 0; mt < 2; mt++) {
            const int r = wm + mt * 16 + g;
            ah[mt][0] = ldu(&AH[st][r][t2]);      ah[mt][1] = ldu(&AH[st][r + 8][t2]);
            ah[mt][2] = ldu(&AH[st][r][t2 + 8]);  ah[mt][3] = ldu(&AH[st][r + 8][t2 + 8]);
            al[mt][0] = ldu(&AL[st][r][t2]);      al[mt][1] = ldu(&AL[st][r + 8][t2]);
            al[mt][2] = ldu(&AL[st][r][t2 + 8]);  al[mt][3] = ldu(&AL[st][r + 8][t2 + 8]);
        }
#pragma unroll
        for (int nt = 0; nt < 8; nt++) {
            const int n = wn + nt * 8 + g;
            uint32_t bh0 = ldu(&BH[st][n][t2]), bh1 = ldu(&BH[st][n][t2 + 8]);
            uint32_t bl0 = ldu(&BL[st][n][t2]), bl1 = ldu(&BL[st][n][t2 + 8]);
#pragma unroll
            for (int mt = 0; mt < 2; mt++) {
                mma16816(acc[mt][nt], ah[mt][0], ah[mt][1], ah[mt][2], ah[mt][3], bh0, bh1);
                mma16816(acc[mt][nt], ah[mt][0], ah[mt][1], ah[mt][2], ah[mt][3], bl0, bl1);
                mma16816(acc[mt][nt], al[mt][0], al[mt][1], al[mt][2], al[mt][3], bh0, bh1);
            }
        }
    }

#pragma unroll
    for (int mt = 0; mt < 2; mt++) {
        const int r = m0 + wm + mt * 16 + g;
#pragma unroll
        for (int nt = 0; nt < 8; nt++) {
            const int col = n0 + wn + nt * 8 + t2;
            const float b0 = dtb[col], b1 = dtb[col + 1];
            *(float2*)&g_dt[(size_t)r * D_INNER + col] =
                make_float2(softplusf(acc[mt][nt][0] + b0), softplusf(acc[mt][nt][1] + b1));
            *(float2*)&g_dt[(size_t)(r + 8) * D_INNER + col] =
                make_float2(softplusf(acc[mt][nt][2] + b0), softplusf(acc[mt][nt][3] + b1));
        }
    }
}

// =====================================================================
// Scan: 256 blocks (2 batches x 128 d-tiles of 32 channels), 128 thr,
// 4 lanes/channel, 4 states/lane, cp.async double-buffered.
// =====================================================================
#define LT 64
#define NTILES (SEQLEN / LT)

__global__ __launch_bounds__(128, 4)
void scan_kernel(const float* __restrict__ x, const float* __restrict__ A_log,
                 const float* __restrict__ Dp, float* __restrict__ y)
{
    extern __shared__ float sm[];
    float* xs  = sm;                   // [2][LT][32]
    float* dts = xs + 2 * LT * 32;     // [2][LT][32]
    float* Bsm = dts + 2 * LT * 32;    // [2][LT][16]
    float* Csm = Bsm + 2 * LT * 16;    // [2][LT][16]

    const int tid = threadIdx.x;
    const int b   = blockIdx.x >> 7;
    const int d0  = (blockIdx.x & 127) * 32;
    const int lane = tid & 31;
    const int w    = tid >> 5;
    const int q    = lane & 3;
    const int cl   = w * 8 + (lane >> 2);
    const int d    = d0 + cl;

    float A2[4];
#pragma unroll
    for (int j = 0; j < 4; j++)
        A2[j] = -__expf(A_log[d * D_STATE + q * 4 + j]) * 1.4426950408889634f;
    const float Dd = Dp[d];

    float h0 = 0.f, h1 = 0.f, h2 = 0.f, h3 = 0.f;

    const float* xg  = x    + (size_t)b * SEQLEN * D_INNER + d0;
    const float* dtg = g_dt + (size_t)b * SEQLEN * D_INNER + d0;
    const float* Bg  = g_xp + (size_t)b * SEQLEN * XPC + DT_RANK;
    const float* Cg  = g_xp + (size_t)b * SEQLEN * XPC + DT_RANK + D_STATE;

    auto load_tile = [&](int t, int buf) {
        const int l0 = t * LT;
        for (int i = tid; i < LT * 8; i += 128) {
            int ll = i >> 3, sg = (i & 7) * 4;
            cp16(&xs [(buf * LT + ll) * 32 + sg], xg  + (size_t)(l0 + ll) * D_INNER + sg);
            cp16(&dts[(buf * LT + ll) * 32 + sg], dtg + (size_t)(l0 + ll) * D_INNER + sg);
        }
        for (int i = tid; i < LT * 4; i += 128) {
            int ll = i >> 2, sg = (i & 3) * 4;
            cp16(&Bsm[(buf * LT + ll) * 16 + sg], Bg + (size_t)(l0 + ll) * XPC + sg);
            cp16(&Csm[(buf * LT + ll) * 16 + sg], Cg + (size_t)(l0 + ll) * XPC + sg);
        }
    };

    load_tile(0, 0);
    cp_commit();

    for (int t = 0; t < NTILES; t++) {
        if (t + 1 < NTILES) {
            load_tile(t + 1, (t + 1) & 1);
            cp_commit();
            cp_wait<1>();
        } else {
            cp_wait<0>();
        }
        __syncthreads();

        const int buf = t & 1;
        const float* xsb  = &xs [buf * LT * 32];
        const float* dtb_ = &dts[buf * LT * 32];
        const float* Bb   = &Bsm[buf * LT * 16];
        const float* Cb   = &Csm[buf * LT * 16];

        float* yout = y + ((size_t)b * SEQLEN + t * LT) * D_INNER + d;

#pragma unroll 4
        for (int ll = 0; ll < LT; ll++) {
            float dtv = dtb_[ll * 32 + cl];
            float xv  = xsb [ll * 32 + cl];
            float4 Bv = *(const float4*)&Bb[ll * 16 + q * 4];
            float4 Cv = *(const float4*)&Cb[ll * 16 + q * 4];

            float dtx = dtv * xv;
            float e0 = ex2f(dtv * A2[0]);
            float e1 = ex2f(dtv * A2[1]);
            float e2 = ex2f(dtv * A2[2]);
            float e3 = ex2f(dtv * A2[3]);
            h0 = fmaf(e0, h0, dtx * Bv.x);
            h1 = fmaf(e1, h1, dtx * Bv.y);
            h2 = fmaf(e2, h2, dtx * Bv.z);
            h3 = fmaf(e3, h3, dtx * Bv.w);

            float p = h0 * Cv.x;
            p = fmaf(h1, Cv.y, p);
            p = fmaf(h2, Cv.z, p);
            p = fmaf(h3, Cv.w, p);
            p += __shfl_xor_sync(0xffffffffu, p, 1);
            p += __shfl_xor_sync(0xffffffffu, p, 2);

            if (q == 0) yout[(size_t)ll * D_INNER] = fmaf(Dd, xv, p);
        }
        __syncthreads();
    }
}

// =====================================================================
// launch
// =====================================================================
extern "C" void kernel_launch(void* const* d_in, const int* in_sizes, int n_in,
                              void* d_out, int out_size)
{
    const float* x     = (const float*)d_in[0];  // (2,512,4096)
    const float* A_log = (const float*)d_in[1];  // (4096,16)
    const float* Dp    = (const float*)d_in[2];  // (4096,)
    const float* xpw   = (const float*)d_in[3];  // (160,4096)
    const float* dtw   = (const float*)d_in[4];  // (4096,128)
    const float* dtb   = (const float*)d_in[5];  // (4096,)
    float* y = (float*)d_out;                    // (2,512,4096)

    convert_xw<<<(XN4 + WN4 + 255) / 256, 256>>>(x, xpw);
    gemm1_kernel<<<dim3(16, KSPLIT), 256>>>();
    reduce_conv<<<(RN4 + DW4 + 255) / 256, 256>>>(dtw);
    gemm2_kernel<<<dim3(8, 32), 256>>>(dtb);
    scan_kernel<<<256, 128, 49152>>>(x, A_log, Dp, y);
}

// round 16
// speedup vs baseline: 1.0004x; 1.0004x over previous
#include <cuda_runtime.h>
#include <cuda_bf16.h>
#include <math.h>
#include <stdint.h>

// ---------------- problem constants ----------------
#define NBATCH   2
#define SEQLEN   512
#define D_INNER  4096
#define D_STATE  16
#define DT_RANK  128
#define NROWS    (NBATCH * SEQLEN)          // 1024
#define XPC      (DT_RANK + 2 * D_STATE)    // 160
#define KSPLIT   16

// ---------------- scratch ----------------
__device__ float g_part[KSPLIT * NROWS * XPC];
__device__ float g_xp[NROWS * XPC];
__device__ float g_dt[NROWS * D_INNER];

__device__ __nv_bfloat16 g_xhi[NROWS * D_INNER], g_xlo[NROWS * D_INNER];
__device__ __nv_bfloat16 g_whi[XPC * D_INNER],   g_wlo[XPC * D_INNER];
__device__ __nv_bfloat16 g_xphi[NROWS * DT_RANK], g_xplo[NROWS * DT_RANK];
__device__ __nv_bfloat16 g_dwhi[D_INNER * DT_RANK], g_dwlo[D_INNER * DT_RANK];

// ---------------- helpers ----------------
__device__ __forceinline__ float ex2f(float v) {
    float r; asm("ex2.approx.ftz.f32 %0, %1;" : "=f"(r) : "f"(v)); return r;
}
__device__ __forceinline__ float softplusf(float z) {
    return fmaxf(z, 0.0f) + log1pf(__expf(-fabsf(z)));
}
__device__ __forceinline__ void cp16(void* dst, const void* src) {
    unsigned s = (unsigned)__cvta_generic_to_shared(dst);
    asm volatile("cp.async.cg.shared.global [%0], [%1], 16;" :: "r"(s), "l"(src));
}
__device__ __forceinline__ void cp_commit() { asm volatile("cp.async.commit_group;"); }
template <int N>
__device__ __forceinline__ void cp_wait() { asm volatile("cp.async.wait_group %0;" :: "n"(N)); }

__device__ __forceinline__ void split2(float x, float y, uint32_t& hi, uint32_t& lo) {
    __nv_bfloat16 hx = __float2bfloat16(x);
    __nv_bfloat16 hy = __float2bfloat16(y);
    float rx = x - __bfloat162float(hx);
    float ry = y - __bfloat162float(hy);
    __nv_bfloat162 H; H.x = hx; H.y = hy;
    __nv_bfloat162 L = __floats2bfloat162_rn(rx, ry);
    hi = *reinterpret_cast<uint32_t*>(&H);
    lo = *reinterpret_cast<uint32_t*>(&L);
}
__device__ __forceinline__ void split4(float4 v, uint2& hi, uint2& lo) {
    split2(v.x, v.y, hi.x, lo.x);
    split2(v.z, v.w, hi.y, lo.y);
}

__device__ __forceinline__ void mma16816(float c[4],
    uint32_t a0, uint32_t a1, uint32_t a2, uint32_t a3, uint32_t b0, uint32_t b1)
{
    asm volatile(
        "mma.sync.aligned.m16n8k16.row.col.f32.bf16.bf16.f32 "
        "{%0,%1,%2,%3}, {%4,%5,%6,%7}, {%8,%9}, {%0,%1,%2,%3};"
        : "+f"(c[0]), "+f"(c[1]), "+f"(c[2]), "+f"(c[3])
        : "r"(a0), "r"(a1), "r"(a2), "r"(a3), "r"(b0), "r"(b1));
}
__device__ __forceinline__ uint32_t ldu(const __nv_bfloat16* p) {
    return *reinterpret_cast<const uint32_t*>(p);
}

#define LDK 24   // bf16 smem row stride: 48B, 16B-aligned, conflict-free

// =====================================================================
// convert_xw: split x (4.2M) and x_proj_w (0.65M) into bf16 hi/lo
// =====================================================================
#define XN4 (NROWS * D_INNER / 4)
#define WN4 (XPC * D_INNER / 4)

__global__ __launch_bounds__(256)
void convert_xw(const float* __restrict__ x, const float* __restrict__ w)
{
    int i = blockIdx.x * 256 + threadIdx.x;
    if (i < XN4) {
        float4 v = ((const float4*)x)[i];
        uint2 hi, lo; split4(v, hi, lo);
        *(uint2*)&g_xhi[4 * (size_t)i] = hi;
        *(uint2*)&g_xlo[4 * (size_t)i] = lo;
    } else if (i < XN4 + WN4) {
        int j = i - XN4;
        float4 v = ((const float4*)w)[j];
        uint2 hi, lo; split4(v, hi, lo);
        *(uint2*)&g_whi[4 * (size_t)j] = hi;
        *(uint2*)&g_wlo[4 * (size_t)j] = lo;
    }
}

// =====================================================================
// GEMM1 (bf16 tensor, 3-stage cp.async):
// part[z][row][c] = sum_{k in slice z} x[row][k]*w[c][k]
// grid (16 Mtiles of 64, 16 ksplits), 256 thr (8 warps: 2M x 4N).
// Kslice 256 = 16 chunks of k16.
// =====================================================================
#define G1_NC 16

__global__ __launch_bounds__(256)
void gemm1_kernel()
{
    __shared__ __nv_bfloat16 AH[3][64][LDK],  AL[3][64][LDK];
    __shared__ __nv_bfloat16 BH[3][160][LDK], BL[3][160][LDK];

    const int tid = threadIdx.x;
    const int m0 = blockIdx.x * 64;
    const int k0 = blockIdx.y * 256;

    const int lane = tid & 31, wid = tid >> 5;
    const int wm = (wid >> 2) * 32;
    const int wn = (wid & 3) * 40;
    const int g = lane >> 2, t2 = (lane & 3) * 2;

    auto load = [&](int c, int st) {
        const int kk = k0 + c * 16;
        for (int s = tid; s < 896; s += 256) {
            if (s < 256) {
                int arr = s >> 7, r = (s >> 1) & 63, half = s & 1;
                const __nv_bfloat16* src =
                    (arr ? g_xlo : g_xhi) + (size_t)(m0 + r) * D_INNER + kk + half * 8;
                __nv_bfloat16* dst = arr ? &AL[st][r][half * 8] : &AH[st][r][half * 8];
                cp16(dst, src);
            } else {
                int s2 = s - 256;
                int arr = s2 / 320, idx = s2 % 320;
                int r = idx >> 1, half = idx & 1;
                const __nv_bfloat16* src =
                    (arr ? g_wlo : g_whi) + (size_t)r * D_INNER + kk + half * 8;
                __nv_bfloat16* dst = arr ? &BL[st][r][half * 8] : &BH[st][r][half * 8];
                cp16(dst, src);
            }
        }
    };

    float acc[2][5][4];
#pragma unroll
    for (int i = 0; i < 2; i++)
#pragma unroll
        for (int j = 0; j < 5; j++)
#pragma unroll
            for (int v = 0; v < 4; v++) acc[i][j][v] = 0.0f;

    load(0, 0); cp_commit();
    load(1, 1); cp_commit();

    for (int c = 0; c < G1_NC; c++) {
        if (c + 1 < G1_NC) cp_wait<1>(); else cp_wait<0>();
        __syncthreads();
        if (c + 2 < G1_NC) { load(c + 2, (c + 2) % 3); cp_commit(); }

        const int st = c % 3;
        uint32_t ah[2][4], al[2][4];
#pragma unroll
        for (int mt = 0; mt < 2; mt++) {
            const int r = wm + mt * 16 + g;
            ah[mt][0] = ldu(&AH[st][r][t2]);      ah[mt][1] = ldu(&AH[st][r + 8][t2]);
            ah[mt][2] = ldu(&AH[st][r][t2 + 8]);  ah[mt][3] = ldu(&AH[st][r + 8][t2 + 8]);
            al[mt][0] = ldu(&AL[st][r][t2]);      al[mt][1] = ldu(&AL[st][r + 8][t2]);
            al[mt][2] = ldu(&AL[st][r][t2 + 8]);  al[mt][3] = ldu(&AL[st][r + 8][t2 + 8]);
        }
#pragma unroll
        for (int nt = 0; nt < 5; nt++) {
            const int n = wn + nt * 8 + g;
            uint32_t bh0 = ldu(&BH[st][n][t2]), bh1 = ldu(&BH[st][n][t2 + 8]);
            uint32_t bl0 = ldu(&BL[st][n][t2]), bl1 = ldu(&BL[st][n][t2 + 8]);
#pragma unroll
            for (int mt = 0; mt < 2; mt++) {
                mma16816(acc[mt][nt], ah[mt][0], ah[mt][1], ah[mt][2], ah[mt][3], bh0, bh1);
                mma16816(acc[mt][nt], ah[mt][0], ah[mt][1], ah[mt][2], ah[mt][3], bl0, bl1);
                mma16816(acc[mt][nt], al[mt][0], al[mt][1], al[mt][2], al[mt][3], bh0, bh1);
            }
        }
    }

    float* outz = g_part + (size_t)blockIdx.y * NROWS * XPC;
#pragma unroll
    for (int mt = 0; mt < 2; mt++) {
        const int r = m0 + wm + mt * 16 + g;
#pragma unroll
        for (int nt = 0; nt < 5; nt++) {
            const int col = wn + nt * 8 + t2;
            *(float2*)&outz[(size_t)r * XPC + col]       = make_float2(acc[mt][nt][0], acc[mt][nt][1]);
            *(float2*)&outz[(size_t)(r + 8) * XPC + col] = make_float2(acc[mt][nt][2], acc[mt][nt][3]);
        }
    }
}

// =====================================================================
// reduce_conv: g_xp = sum_z g_part[z]; also split xp[:, :128] and dtw
// to bf16 hi/lo for GEMM2.
// =====================================================================
#define RN4  (NROWS * XPC / 4)          // 40960
#define DW4  (D_INNER * DT_RANK / 4)    // 131072

__global__ __launch_bounds__(256)
void reduce_conv(const float* __restrict__ dtw)
{
    int i = blockIdx.x * 256 + threadIdx.x;
    if (i < RN4) {
        const float4* p = (const float4*)g_part;
        float4 s = p[i];
#pragma unroll
        for (int z = 1; z < KSPLIT; z++) {
            float4 v = p[(size_t)z * RN4 + i];
            s.x += v.x; s.y += v.y; s.z += v.z; s.w += v.w;
        }
        ((float4*)g_xp)[i] = s;
        int row = i / (XPC / 4), col4 = i % (XPC / 4);
        if (col4 < DT_RANK / 4) {
            uint2 hi, lo; split4(s, hi, lo);
            size_t o = (size_t)row * DT_RANK + col4 * 4;
            *(uint2*)&g_xphi[o] = hi;
            *(uint2*)&g_xplo[o] = lo;
        }
    } else if (i < RN4 + DW4) {
        int j = i - RN4;
        float4 v = ((const float4*)dtw)[j];
        uint2 hi, lo; split4(v, hi, lo);
        *(uint2*)&g_dwhi[4 * (size_t)j] = hi;
        *(uint2*)&g_dwlo[4 * (size_t)j] = lo;
    }
}

// =====================================================================
// GEMM2 (bf16 tensor, 3-stage cp.async):
// g_dt[row][d] = softplus(sum_r xp[row][r]*dtw[d][r] + b[d])
// grid (8 Mtiles of 128, 32 Ntiles of 128), 256 thr (8 warps: 4M x 2N).
// K=128 = 8 chunks of 16.
// =====================================================================
#define G2_NC 8

__global__ __launch_bounds__(256)
void gemm2_kernel(const float* __restrict__ dtb)
{
    __shared__ __nv_bfloat16 AH[3][128][LDK], AL[3][128][LDK];
    __shared__ __nv_bfloat16 BH[3][128][LDK], BL[3][128][LDK];

    const int tid = threadIdx.x;
    const int m0 = blockIdx.x * 128;
    const int n0 = blockIdx.y * 128;

    const int lane = tid & 31, wid = tid >> 5;
    const int wm = (wid >> 1) * 32;
    const int wn = (wid & 1) * 64;
    const int g = lane >> 2, t2 = (lane & 3) * 2;

    auto load = [&](int c, int st) {
        const int kk = c * 16;
        for (int s = tid; s < 1024; s += 256) {
            int which = s >> 9;          // 0 = A, 1 = B
            int s2 = s & 511;
            int arr = s2 >> 8, idx = s2 & 255;
            int r = idx >> 1, half = idx & 1;
            const __nv_bfloat16* src;
            __nv_bfloat16* dst;
            if (which == 0) {
                src = (arr ? g_xplo : g_xphi) + (size_t)(m0 + r) * DT_RANK + kk + half * 8;
                dst = arr ? &AL[st][r][half * 8] : &AH[st][r][half * 8];
            } else {
                src = (arr ? g_dwlo : g_dwhi) + (size_t)(n0 + r) * DT_RANK + kk + half * 8;
                dst = arr ? &BL[st][r][half * 8] : &BH[st][r][half * 8];
            }
            cp16(dst, src);
        }
    };

    float acc[2][8][4];
#pragma unroll
    for (int i = 0; i < 2; i++)
#pragma unroll
        for (int j = 0; j < 8; j++)
#pragma unroll
            for (int v = 0; v < 4; v++) acc[i][j][v] = 0.0f;

    load(0, 0); cp_commit();
    load(1, 1); cp_commit();

    for (int c = 0; c < G2_NC; c++) {
        if (c + 1 < G2_NC) cp_wait<1>(); else cp_wait<0>();
        __syncthreads();
        if (c + 2 < G2_NC) { load(c + 2, (c + 2) % 3); cp_commit(); }

        const int st = c % 3;
        uint32_t ah[2][4], al[2][4];
#pragma unroll
        for (int mt = 0; mt < 2; mt++) {
            const int r = wm + mt * 16 + g;
            ah[mt][0] = ldu(&AH[st][r][t2]);      ah[mt][1] = ldu(&AH[st][r + 8][t2]);
            ah[mt][2] = ldu(&AH[st][r][t2 + 8]);  ah[mt][3] = ldu(&AH[st][r + 8][t2 + 8]);
            al[mt][0] = ldu(&AL[st][r][t2]);      al[mt][1] = ldu(&AL[st][r + 8][t2]);
            al[mt][2] = ldu(&AL[st][r][t2 + 8]);  al[mt][3] = ldu(&AL[st][r + 8][t2 + 8]);
        }
#pragma unroll
        for (int nt = 0; nt < 8; nt++) {
            const int n = wn + nt * 8 + g;
            uint32_t bh0 = ldu(&BH[st][n][t2]), bh1 = ldu(&BH[st][n][t2 + 8]);
            uint32_t bl0 = ldu(&BL[st][n][t2]), bl1 = ldu(&BL[st][n][t2 + 8]);
#pragma unroll
            for (int mt = 0; mt < 2; mt++) {
                mma16816(acc[mt][nt], ah[mt][0], ah[mt][1], ah[mt][2], ah[mt][3], bh0, bh1);
                mma16816(acc[mt][nt], ah[mt][0], ah[mt][1], ah[mt][2], ah[mt][3], bl0, bl1);
                mma16816(acc[mt][nt], al[mt][0], al[mt][1], al[mt][2], al[mt][3], bh0, bh1);
            }
        }
    }

#pragma unroll
    for (int mt = 0; mt < 2; mt++) {
        const int r = m0 + wm + mt * 16 + g;
#pragma unroll
        for (int nt = 0; nt < 8; nt++) {
            const int col = n0 + wn + nt * 8 + t2;
            const float b0 = dtb[col], b1 = dtb[col + 1];
            *(float2*)&g_dt[(size_t)r * D_INNER + col] =
                make_float2(softplusf(acc[mt][nt][0] + b0), softplusf(acc[mt][nt][1] + b1));
            *(float2*)&g_dt[(size_t)(r + 8) * D_INNER + col] =
                make_float2(softplusf(acc[mt][nt][2] + b0), softplusf(acc[mt][nt][3] + b1));
        }
    }
}

// =====================================================================
// Scan: 256 blocks (2 batches x 128 d-tiles of 32 channels), 128 thr,
// 4 lanes/channel, 4 states/lane, cp.async double-buffered.
// =====================================================================
#define LT 64
#define NTILES (SEQLEN / LT)

__global__ __launch_bounds__(128, 4)
void scan_kernel(const float* __restrict__ x, const float* __restrict__ A_log,
                 const float* __restrict__ Dp, float* __restrict__ y)
{
    extern __shared__ float sm[];
    float* xs  = sm;                   // [2][LT][32]
    float* dts = xs + 2 * LT * 32;     // [2][LT][32]
    float* Bsm = dts + 2 * LT * 32;    // [2][LT][16]
    float* Csm = Bsm + 2 * LT * 16;    // [2][LT][16]

    const int tid = threadIdx.x;
    const int b   = blockIdx.x >> 7;
    const int d0  = (blockIdx.x & 127) * 32;
    const int lane = tid & 31;
    const int w    = tid >> 5;
    const int q    = lane & 3;
    const int cl   = w * 8 + (lane >> 2);
    const int d    = d0 + cl;

    float A2[4];
#pragma unroll
    for (int j = 0; j < 4; j++)
        A2[j] = -__expf(A_log[d * D_STATE + q * 4 + j]) * 1.4426950408889634f;
    const float Dd = Dp[d];

    float h0 = 0.f, h1 = 0.f, h2 = 0.f, h3 = 0.f;

    const float* xg  = x    + (size_t)b * SEQLEN * D_INNER + d0;
    const float* dtg = g_dt + (size_t)b * SEQLEN * D_INNER + d0;
    const float* Bg  = g_xp + (size_t)b * SEQLEN * XPC + DT_RANK;
    const float* Cg  = g_xp + (size_t)b * SEQLEN * XPC + DT_RANK + D_STATE;

    auto load_tile = [&](int t, int buf) {
        const int l0 = t * LT;
        for (int i = tid; i < LT * 8; i += 128) {
            int ll = i >> 3, sg = (i & 7) * 4;
            cp16(&xs [(buf * LT + ll) * 32 + sg], xg  + (size_t)(l0 + ll) * D_INNER + sg);
            cp16(&dts[(buf * LT + ll) * 32 + sg], dtg + (size_t)(l0 + ll) * D_INNER + sg);
        }
        for (int i = tid; i < LT * 4; i += 128) {
            int ll = i >> 2, sg = (i & 3) * 4;
            cp16(&Bsm[(buf * LT + ll) * 16 + sg], Bg + (size_t)(l0 + ll) * XPC + sg);
            cp16(&Csm[(buf * LT + ll) * 16 + sg], Cg + (size_t)(l0 + ll) * XPC + sg);
        }
    };

    load_tile(0, 0);
    cp_commit();

    for (int t = 0; t < NTILES; t++) {
        if (t + 1 < NTILES) {
            load_tile(t + 1, (t + 1) & 1);
            cp_commit();
            cp_wait<1>();
        } else {
            cp_wait<0>();
        }
        __syncthreads();

        const int buf = t & 1;
        const float* xsb  = &xs [buf * LT * 32];
        const float* dtb_ = &dts[buf * LT * 32];
        const float* Bb   = &Bsm[buf * LT * 16];
        const float* Cb   = &Csm[buf * LT * 16];

        float* yout = y + ((size_t)b * SEQLEN + t * LT) * D_INNER + d;

#pragma unroll 4
        for (int ll = 0; ll < LT; ll++) {
            float dtv = dtb_[ll * 32 + cl];
            float xv  = xsb [ll * 32 + cl];
            float4 Bv = *(const float4*)&Bb[ll * 16 + q * 4];
            float4 Cv = *(const float4*)&Cb[ll * 16 + q * 4];

            float dtx = dtv * xv;
            float e0 = ex2f(dtv * A2[0]);
            float e1 = ex2f(dtv * A2[1]);
            float e2 = ex2f(dtv * A2[2]);
            float e3 = ex2f(dtv * A2[3]);
            h0 = fmaf(e0, h0, dtx * Bv.x);
            h1 = fmaf(e1, h1, dtx * Bv.y);
            h2 = fmaf(e2, h2, dtx * Bv.z);
            h3 = fmaf(e3, h3, dtx * Bv.w);

            float p = h0 * Cv.x;
            p = fmaf(h1, Cv.y, p);
            p = fmaf(h2, Cv.z, p);
            p = fmaf(h3, Cv.w, p);
            p += __shfl_xor_sync(0xffffffffu, p, 1);
            p += __shfl_xor_sync(0xffffffffu, p, 2);

            if (q == 0) yout[(size_t)ll * D_INNER] = fmaf(Dd, xv, p);
        }
        __syncthreads();
    }
}

// =====================================================================
// launch
// =====================================================================
extern "C" void kernel_launch(void* const* d_in, const int* in_sizes, int n_in,
                              void* d_out, int out_size)
{
    const float* x     = (const float*)d_in[0];  // (2,512,4096)
    const float* A_log = (const float*)d_in[1];  // (4096,16)
    const float* Dp    = (const float*)d_in[2];  // (4096,)
    const float* xpw   = (const float*)d_in[3];  // (160,4096)
    const float* dtw   = (const float*)d_in[4];  // (4096,128)
    const float* dtb   = (const float*)d_in[5];  // (4096,)
    float* y = (float*)d_out;                    // (2,512,4096)

    convert_xw<<<(XN4 + WN4 + 255) / 256, 256>>>(x, xpw);
    gemm1_kernel<<<dim3(16, KSPLIT), 256>>>();
    reduce_conv<<<(RN4 + DW4 + 255) / 256, 256>>>(dtw);
    gemm2_kernel<<<dim3(8, 32), 256>>>(dtb);
    scan_kernel<<<256, 128, 49152>>>(x, A_log, Dp, y);
}